// round 4
// baseline (speedup 1.0000x reference)
#include <cuda_runtime.h>

typedef unsigned long long u64;

#define BATCH 8
#define CH    64
#define HW    4096
#define CQn   8
#define CVn   32
#define NP    1024   // pooled pixels per batch (32x32)
#define EPSBN 1e-5f
#define LOG2E 1.4426950408889634f

// ---------------- precomputed Q/K/V (K pre-scaled by log2e) ----------------
__device__ float g_Q[(size_t)BATCH*HW*CQn];   // [b][n][8]
__device__ float g_K[(size_t)BATCH*NP*CQn];   // [b][m][8]  (x log2e)
__device__ float g_V[(size_t)BATCH*NP*CVn];   // [b][m][32]

// ---------------- f32x2 helpers (Blackwell packed fp32) ----------------
__device__ __forceinline__ u64 pk2(float lo, float hi) {
    u64 r; asm("mov.b64 %0,{%1,%2};" : "=l"(r) : "f"(lo), "f"(hi)); return r;
}
__device__ __forceinline__ void upk2(u64 v, float& lo, float& hi) {
    asm("mov.b64 {%0,%1},%2;" : "=f"(lo), "=f"(hi) : "l"(v));
}
__device__ __forceinline__ u64 ffma2(u64 a, u64 b, u64 c) {
    u64 d; asm("fma.rn.f32x2 %0,%1,%2,%3;" : "=l"(d) : "l"(a), "l"(b), "l"(c)); return d;
}
__device__ __forceinline__ u64 fmul2(u64 a, u64 b) {
    u64 d; asm("mul.rn.f32x2 %0,%1,%2;" : "=l"(d) : "l"(a), "l"(b)); return d;
}
__device__ __forceinline__ float ex2(float x) {
    float y; asm("ex2.approx.f32 %0,%1;" : "=f"(y) : "f"(x)); return y;
}

// ---------------- kernel 1: Q (full-res) + pooled K/V, BN folded in-CTA ----
// One CTA per (batch, 2-row strip): rows 2*h2, 2*h2+1 (128 px), pooled row h2.
__global__ __launch_bounds__(256) void prep_kernel(
    const float* __restrict__ mem,
    const float* __restrict__ wq, const float* __restrict__ bq,
    const float* __restrict__ qs, const float* __restrict__ qb,
    const float* __restrict__ qm, const float* __restrict__ qv,
    const float* __restrict__ wk, const float* __restrict__ bk,
    const float* __restrict__ ks, const float* __restrict__ kb,
    const float* __restrict__ km, const float* __restrict__ kv,
    const float* __restrict__ wv, const float* __restrict__ bv,
    const float* __restrict__ vs, const float* __restrict__ vb,
    const float* __restrict__ vm, const float* __restrict__ vv)
{
    __shared__ float tile[CH*128];      // 32 KB: [ch][128 px]
    __shared__ float wqs[CQn*CH];
    __shared__ float wks[CQn*CH];
    __shared__ float wvs[CVn*CH];
    __shared__ float cqs[CQn], cks[CQn], cvs[CVn];

    int t  = threadIdx.x;
    int b  = blockIdx.x >> 5;
    int h2 = blockIdx.x & 31;

    // fold BN into weights (per-CTA, tiny)
    for (int i = t; i < CQn*CH; i += 256) {
        int c = i >> 6;
        float iq = qs[c] * rsqrtf(qv[c] + EPSBN);
        float ik = ks[c] * rsqrtf(kv[c] + EPSBN);
        wqs[i] = wq[i] * iq;
        wks[i] = wk[i] * ik * LOG2E;
    }
    for (int i = t; i < CVn*CH; i += 256) {
        int c = i >> 6;
        float iv = vs[c] * rsqrtf(vv[c] + EPSBN);
        wvs[i] = wv[i] * iv;
    }
    if (t < CQn) {
        float iq = qs[t] * rsqrtf(qv[t] + EPSBN);
        float ik = ks[t] * rsqrtf(kv[t] + EPSBN);
        cqs[t] = bq[t]*iq + qb[t] - qm[t]*iq;
        cks[t] = (bk[t]*ik + kb[t] - km[t]*ik) * LOG2E;
    }
    if (t < CVn) {
        float iv = vs[t] * rsqrtf(vv[t] + EPSBN);
        cvs[t] = bv[t]*iv + vb[t] - vm[t]*iv;
    }

    // load 64ch x 128px strip (each channel: 128 contiguous floats)
    const float4* src = (const float4*)(mem + (size_t)b*CH*HW + (size_t)h2*128);
    float4* t4 = (float4*)tile;
    for (int i = t; i < CH*32; i += 256) {
        int c = i >> 5, j = i & 31;
        t4[i] = src[(size_t)c*(HW/4) + j];
    }
    __syncthreads();

    // ---- Q: 8 ch x 128 px ; thread -> (4 ch, 1 px)
    {
        int p = t & 127, half = t >> 7;
        int oc0 = half * 4;
        float a0 = 0.f, a1 = 0.f, a2 = 0.f, a3 = 0.f;
        const float* w0 = &wqs[oc0*CH];
        #pragma unroll 8
        for (int ch = 0; ch < CH; ch++) {
            float m = tile[ch*128 + p];
            a0 += w0[ch      ]*m;
            a1 += w0[CH  +ch ]*m;
            a2 += w0[2*CH+ch ]*m;
            a3 += w0[3*CH+ch ]*m;
        }
        size_t n = (size_t)b*HW + h2*128 + p;
        float4 o = make_float4(a0 + cqs[oc0], a1 + cqs[oc0+1],
                               a2 + cqs[oc0+2], a3 + cqs[oc0+3]);
        *(float4*)&g_Q[n*CQn + oc0] = o;
    }

    // ---- K pooled: 8 ch x 32 pooled ; thread -> (1 ch, 1 pooled px, 4 src px)
    {
        int i = t & 31, oc = t >> 5;
        float a0 = 0.f, a1 = 0.f, a2 = 0.f, a3 = 0.f;
        const float* w = &wks[oc*CH];
        int p0 = 2*i, p2 = 64 + 2*i;
        #pragma unroll 4
        for (int ch = 0; ch < CH; ch++) {
            float wv_ = w[ch];
            const float* tr = &tile[ch*128];
            a0 += wv_*tr[p0];   a1 += wv_*tr[p0+1];
            a2 += wv_*tr[p2];   a3 += wv_*tr[p2+1];
        }
        float mx = fmaxf(fmaxf(a0,a1), fmaxf(a2,a3)) + cks[oc];
        g_K[((size_t)b*NP + h2*32 + i)*CQn + oc] = mx;
    }

    // ---- V pooled: 32 ch x 32 pooled ; thread -> (4 ch, 1 pooled px, 4 src px)
    {
        int i = t & 31, gr = t >> 5;
        int oc0 = gr * 4;
        float acc[4][4];
        #pragma unroll
        for (int a = 0; a < 4; a++)
            #pragma unroll
            for (int c = 0; c < 4; c++) acc[a][c] = 0.f;
        int p0 = 2*i, p2 = 64 + 2*i;
        #pragma unroll 2
        for (int ch = 0; ch < CH; ch++) {
            const float* tr = &tile[ch*128];
            float m0 = tr[p0], m1 = tr[p0+1], m2 = tr[p2], m3 = tr[p2+1];
            #pragma unroll
            for (int a = 0; a < 4; a++) {
                float wv_ = wvs[(oc0+a)*CH + ch];
                acc[a][0] += wv_*m0; acc[a][1] += wv_*m1;
                acc[a][2] += wv_*m2; acc[a][3] += wv_*m3;
            }
        }
        float4 o;
        float* op = &o.x;
        #pragma unroll
        for (int a = 0; a < 4; a++)
            op[a] = fmaxf(fmaxf(acc[a][0],acc[a][1]),
                          fmaxf(acc[a][2],acc[a][3])) + cvs[oc0+a];
        *(float4*)&g_V[((size_t)b*NP + h2*32 + i)*CVn + oc0] = o;
    }
}

// ---------------- kernel 2: fused attention + projection + residual -------
// grid (16 q-tiles, 8 batches), 256 threads = 1 query/thread.
// K (32KB) + V (128KB) + folded wp (8KB) resident in SMEM; reads broadcast.
// Single-pass online softmax, chunks of 16 keys.
#define CHUNK 16
#define SMEM_B_FLOATS (NP*CVn + NP*CQn + CH*CVn + CH)
#define SMEM_B_BYTES  (SMEM_B_FLOATS * 4)

__global__ __launch_bounds__(256) void attn_kernel(
    const float* __restrict__ x, float* __restrict__ out,
    const float* __restrict__ wp, const float* __restrict__ bp,
    const float* __restrict__ ps, const float* __restrict__ pb,
    const float* __restrict__ pm, const float* __restrict__ pv,
    const float* __restrict__ gamma)
{
    extern __shared__ float sm[];
    float* Vs  = sm;                    // [NP][32]
    float* Ksm = sm + NP*CVn;           // [NP][8]
    float* wps = Ksm + NP*CQn;          // [64][32]
    float* cps = wps + CH*CVn;          // [64]

    int t = threadIdx.x;
    int b = blockIdx.y;
    float gam = gamma[0];

    {
        const float4* sv = (const float4*)&g_V[(size_t)b*NP*CVn];
        float4* dv = (float4*)Vs;
        for (int i = t; i < NP*CVn/4; i += 256) dv[i] = sv[i];
        const float4* sk = (const float4*)&g_K[(size_t)b*NP*CQn];
        float4* dk = (float4*)Ksm;
        for (int i = t; i < NP*CQn/4; i += 256) dk[i] = sk[i];
        // fold BN+gamma into projection weights (per-CTA)
        for (int i = t; i < CH*CVn; i += 256) {
            int c = i >> 5;
            float ip = ps[c] * rsqrtf(pv[c] + EPSBN);
            wps[i] = gam * ip * wp[i];
        }
        for (int c = t; c < CH; c += 256) {
            float ip = ps[c] * rsqrtf(pv[c] + EPSBN);
            cps[c] = gam * (bp[c]*ip + pb[c] - pm[c]*ip);
        }
    }
    __syncthreads();

    int nq = blockIdx.x*256 + t;   // pixel index within batch [0,4096)
    const float4* qp = (const float4*)&g_Q[((size_t)b*HW + nq)*CQn];
    float4 qA = qp[0], qB = qp[1];
    u64 q01 = pk2(qA.x, qA.y), q23 = pk2(qA.z, qA.w);
    u64 q45 = pk2(qB.x, qB.y), q67 = pk2(qB.z, qB.w);

    const ulonglong2* KK = (const ulonglong2*)Ksm;
    const ulonglong2* VV = (const ulonglong2*)Vs;

    // ---- single pass: online softmax (chunked) + weighted V accumulation
    float mx = -1e30f;
    float s  = 0.f;
    u64 acc[16];
    #pragma unroll
    for (int i = 0; i < 16; i++) acc[i] = 0ULL;

    #pragma unroll 1
    for (int m0 = 0; m0 < NP; m0 += CHUNK) {
        const ulonglong2* kr = KK + 2*(size_t)m0;
        float l[CHUNK];
        float cmax = -1e30f;
        #pragma unroll
        for (int j = 0; j < CHUNK; j++) {
            ulonglong2 k0 = kr[2*j], k1 = kr[2*j+1];
            u64 d = fmul2(q01, k0.x);
            d = ffma2(q23, k0.y, d);
            d = ffma2(q45, k1.x, d);
            d = ffma2(q67, k1.y, d);
            float lo, hi; upk2(d, lo, hi);
            l[j] = lo + hi;                 // log2-scale logit
            cmax = fmaxf(cmax, l[j]);
        }
        if (cmax > mx) {                    // rare after warm-up
            float f = ex2(mx - cmax);
            mx = cmax;
            s *= f;
            u64 f2 = pk2(f, f);
            #pragma unroll
            for (int i = 0; i < 16; i++) acc[i] = fmul2(acc[i], f2);
        }
        #pragma unroll
        for (int j = 0; j < CHUNK; j++) {
            float e = ex2(l[j] - mx);
            s += e;
            u64 e2 = pk2(e, e);
            const ulonglong2* vr = VV + (size_t)(m0 + j)*8;
            #pragma unroll
            for (int i = 0; i < 8; i++) {
                ulonglong2 v2 = vr[i];
                acc[2*i  ] = ffma2(e2, v2.x, acc[2*i  ]);
                acc[2*i+1] = ffma2(e2, v2.y, acc[2*i+1]);
            }
        }
    }

    float inv = 1.0f / s;          // s >= 1 (max term contributes 2^0 = 1)
    u64 inv2 = pk2(inv, inv);
    u64 gp[16];
    #pragma unroll
    for (int i = 0; i < 16; i++) gp[i] = fmul2(acc[i], inv2);

    // ---- folded projection (wp*BN*gamma) + residual
    const ulonglong2* W2 = (const ulonglong2*)wps;
    size_t base = (size_t)b*CH*HW + nq;
    #pragma unroll 4
    for (int c = 0; c < CH; c++) {
        const ulonglong2* wr = W2 + (size_t)c*8;
        u64 d = 0ULL;
        #pragma unroll
        for (int i = 0; i < 8; i++) {
            ulonglong2 w2 = wr[i];
            d = ffma2(gp[2*i  ], w2.x, d);
            d = ffma2(gp[2*i+1], w2.y, d);
        }
        float lo, hi; upk2(d, lo, hi);
        float val = lo + hi + cps[c];
        out[base + (size_t)c*HW] = __ldg(&x[base + (size_t)c*HW]) + val;
    }
}

// ---------------- launch ----------------
extern "C" void kernel_launch(void* const* d_in, const int* in_sizes, int n_in,
                              void* d_out, int out_size)
{
    (void)in_sizes; (void)n_in; (void)out_size;
    const float* x   = (const float*)d_in[0];
    const float* mem = (const float*)d_in[1];

    cudaFuncSetAttribute(attn_kernel,
                         cudaFuncAttributeMaxDynamicSharedMemorySize, SMEM_B_BYTES);

    prep_kernel<<<BATCH*32, 256>>>(mem,
        (const float*)d_in[2],  (const float*)d_in[3],  (const float*)d_in[4],
        (const float*)d_in[5],  (const float*)d_in[6],  (const float*)d_in[7],
        (const float*)d_in[8],  (const float*)d_in[9],  (const float*)d_in[10],
        (const float*)d_in[11], (const float*)d_in[12], (const float*)d_in[13],
        (const float*)d_in[14], (const float*)d_in[15], (const float*)d_in[16],
        (const float*)d_in[17], (const float*)d_in[18], (const float*)d_in[19]);

    attn_kernel<<<dim3(16, BATCH), 256, SMEM_B_BYTES>>>(x, (float*)d_out,
        (const float*)d_in[20], (const float*)d_in[21], (const float*)d_in[22],
        (const float*)d_in[23], (const float*)d_in[24], (const float*)d_in[25],
        (const float*)d_in[26]);
}

// round 5
// speedup vs baseline: 2.3027x; 2.3027x over previous
#include <cuda_runtime.h>
#include <cstdint>

typedef unsigned int u32;
typedef unsigned long long u64;

#define BATCH 8
#define CH    64
#define HW    4096
#define CQn   8
#define CVn   32
#define NP    1024
#define NCH   64          // 16-key chunks
#define EPSBN 1e-5f
#define LOG2E 1.4426950408889634f

__device__ float g_Q[(size_t)BATCH*HW*CQn];   // [b][n][8]
__device__ float g_K[(size_t)BATCH*NP*CQn];   // [b][m][8]  (x log2e)
__device__ float g_V[(size_t)BATCH*NP*CVn];   // [b][m][32]

// ---------------- helpers ----------------
__device__ __forceinline__ u64 pk2(float lo, float hi) {
    u64 r; asm("mov.b64 %0,{%1,%2};" : "=l"(r) : "f"(lo), "f"(hi)); return r;
}
__device__ __forceinline__ void upk2(u64 v, float& lo, float& hi) {
    asm("mov.b64 {%0,%1},%2;" : "=f"(lo), "=f"(hi) : "l"(v));
}
__device__ __forceinline__ u64 ffma2(u64 a, u64 b, u64 c) {
    u64 d; asm("fma.rn.f32x2 %0,%1,%2,%3;" : "=l"(d) : "l"(a), "l"(b), "l"(c)); return d;
}
__device__ __forceinline__ float ex2f(float x) {
    float y; asm("ex2.approx.f32 %0,%1;" : "=f"(y) : "f"(x)); return y;
}
__device__ __forceinline__ u32 pkh(float a, float b) {   // a->lo, b->hi
    u32 r; asm("cvt.rn.f16x2.f32 %0,%1,%2;" : "=r"(r) : "f"(b), "f"(a)); return r;
}
__device__ __forceinline__ void hsplit(float a, float b, u32& hi, u32& lo) {
    u32 h = pkh(a, b);
    float fa, fb;
    asm("{.reg .b16 x,y; mov.b32 {x,y},%2; cvt.f32.f16 %0,x; cvt.f32.f16 %1,y;}"
        : "=f"(fa), "=f"(fb) : "r"(h));
    hi = h; lo = pkh(a - fa, b - fb);
}
__device__ __forceinline__ void mma16816(float* d, const u32* a, u32 b0, u32 b1) {
    asm("mma.sync.aligned.m16n8k16.row.col.f32.f16.f16.f32 "
        "{%0,%1,%2,%3},{%4,%5,%6,%7},{%8,%9},{%0,%1,%2,%3};"
        : "+f"(d[0]), "+f"(d[1]), "+f"(d[2]), "+f"(d[3])
        : "r"(a[0]), "r"(a[1]), "r"(a[2]), "r"(a[3]), "r"(b0), "r"(b1));
}

// ---------------- kernel 1: Q + pooled K/V (unchanged, proven) ----------------
__global__ __launch_bounds__(256) void prep_kernel(
    const float* __restrict__ mem,
    const float* __restrict__ wq, const float* __restrict__ bq,
    const float* __restrict__ qs, const float* __restrict__ qb,
    const float* __restrict__ qm, const float* __restrict__ qv,
    const float* __restrict__ wk, const float* __restrict__ bk,
    const float* __restrict__ ks, const float* __restrict__ kb,
    const float* __restrict__ km, const float* __restrict__ kv,
    const float* __restrict__ wv, const float* __restrict__ bv,
    const float* __restrict__ vs, const float* __restrict__ vb,
    const float* __restrict__ vm, const float* __restrict__ vv)
{
    __shared__ float tile[CH*128];
    __shared__ float wqs[CQn*CH], wks[CQn*CH], wvs[CVn*CH];
    __shared__ float cqs[CQn], cks[CQn], cvs[CVn];

    int t  = threadIdx.x;
    int b  = blockIdx.x >> 5;
    int h2 = blockIdx.x & 31;

    for (int i = t; i < CQn*CH; i += 256) {
        int c = i >> 6;
        float iq = qs[c] * rsqrtf(qv[c] + EPSBN);
        float ik = ks[c] * rsqrtf(kv[c] + EPSBN);
        wqs[i] = wq[i] * iq;
        wks[i] = wk[i] * ik * LOG2E;
    }
    for (int i = t; i < CVn*CH; i += 256) {
        int c = i >> 6;
        float iv = vs[c] * rsqrtf(vv[c] + EPSBN);
        wvs[i] = wv[i] * iv;
    }
    if (t < CQn) {
        float iq = qs[t] * rsqrtf(qv[t] + EPSBN);
        float ik = ks[t] * rsqrtf(kv[t] + EPSBN);
        cqs[t] = bq[t]*iq + qb[t] - qm[t]*iq;
        cks[t] = (bk[t]*ik + kb[t] - km[t]*ik) * LOG2E;
    }
    if (t < CVn) {
        float iv = vs[t] * rsqrtf(vv[t] + EPSBN);
        cvs[t] = bv[t]*iv + vb[t] - vm[t]*iv;
    }

    const float4* src = (const float4*)(mem + (size_t)b*CH*HW + (size_t)h2*128);
    float4* t4 = (float4*)tile;
    for (int i = t; i < CH*32; i += 256) {
        int c = i >> 5, j = i & 31;
        t4[i] = src[(size_t)c*(HW/4) + j];
    }
    __syncthreads();

    {   // Q
        int p = t & 127, half = t >> 7;
        int oc0 = half * 4;
        float a0 = 0.f, a1 = 0.f, a2 = 0.f, a3 = 0.f;
        const float* w0 = &wqs[oc0*CH];
        #pragma unroll 8
        for (int ch = 0; ch < CH; ch++) {
            float m = tile[ch*128 + p];
            a0 += w0[ch]*m; a1 += w0[CH+ch]*m;
            a2 += w0[2*CH+ch]*m; a3 += w0[3*CH+ch]*m;
        }
        size_t n = (size_t)b*HW + h2*128 + p;
        float4 o = make_float4(a0 + cqs[oc0], a1 + cqs[oc0+1],
                               a2 + cqs[oc0+2], a3 + cqs[oc0+3]);
        *(float4*)&g_Q[n*CQn + oc0] = o;
    }
    {   // K pooled
        int i = t & 31, oc = t >> 5;
        float a0 = 0.f, a1 = 0.f, a2 = 0.f, a3 = 0.f;
        const float* w = &wks[oc*CH];
        int p0 = 2*i, p2 = 64 + 2*i;
        #pragma unroll 4
        for (int ch = 0; ch < CH; ch++) {
            float wv_ = w[ch];
            const float* tr = &tile[ch*128];
            a0 += wv_*tr[p0]; a1 += wv_*tr[p0+1];
            a2 += wv_*tr[p2]; a3 += wv_*tr[p2+1];
        }
        float mx = fmaxf(fmaxf(a0,a1), fmaxf(a2,a3)) + cks[oc];
        g_K[((size_t)b*NP + h2*32 + i)*CQn + oc] = mx;
    }
    {   // V pooled
        int i = t & 31, gr = t >> 5;
        int oc0 = gr * 4;
        float acc[4][4];
        #pragma unroll
        for (int a = 0; a < 4; a++)
            #pragma unroll
            for (int c = 0; c < 4; c++) acc[a][c] = 0.f;
        int p0 = 2*i, p2 = 64 + 2*i;
        #pragma unroll 2
        for (int ch = 0; ch < CH; ch++) {
            const float* tr = &tile[ch*128];
            float m0 = tr[p0], m1 = tr[p0+1], m2 = tr[p2], m3 = tr[p2+1];
            #pragma unroll
            for (int a = 0; a < 4; a++) {
                float wv_ = wvs[(oc0+a)*CH + ch];
                acc[a][0] += wv_*m0; acc[a][1] += wv_*m1;
                acc[a][2] += wv_*m2; acc[a][3] += wv_*m3;
            }
        }
        float4 o; float* op = &o.x;
        #pragma unroll
        for (int a = 0; a < 4; a++)
            op[a] = fmaxf(fmaxf(acc[a][0],acc[a][1]),
                          fmaxf(acc[a][2],acc[a][3])) + cvs[oc0+a];
        *(float4*)&g_V[((size_t)b*NP + h2*32 + i)*CVn + oc0] = o;
    }
}

// ---------------- kernel 2: tensor-core flash attention ----------------
// 8 warps x 32 queries = 256 q/CTA; grid (16, BATCH) = single wave.
#define SKF_N 2048                       // NCH*32 uint4
#define SVF_N 8192                       // NCH*4*32 uint4
#define SMEM_ATTN ((SKF_N + SVF_N)*16 + CH*CVn*4 + CH*4)

__global__ __launch_bounds__(256, 1) void attn_kernel(
    const float* __restrict__ x, float* __restrict__ out,
    const float* __restrict__ wp, const float* __restrict__ bp,
    const float* __restrict__ ps, const float* __restrict__ pb,
    const float* __restrict__ pm, const float* __restrict__ pv,
    const float* __restrict__ gamma)
{
    extern __shared__ char smem[];
    uint4* sKf = (uint4*)smem;           // [chunk][lane] {kh0,kl0,kh1,kl1}
    uint4* sVf = sKf + SKF_N;            // [chunk][j][lane] {vh0,vh1,vl0,vl1}
    float* sWp = (float*)(sVf + SVF_N);  // [ch][32]
    float* sCp = sWp + CH*CVn;
    float* sG  = (float*)smem;           // alias after loop: [256 q][stride 33]

    int t = threadIdx.x, lane = t & 31, wid = t >> 5;
    int g = lane >> 2, tq = lane & 3;
    int b = blockIdx.y;
    float gam = gamma[0];

    // ---- copy-in: build K/V MMA fragments from fp32 (hi/lo f16 split)
    const float* Kb = &g_K[(size_t)b*NP*CQn];
    for (int e = t; e < SKF_N; e += 256) {
        int c = e >> 5;
        int k0 = c*16 + g, k1 = k0 + 8;
        u32 h0,l0,h1,l1;
        hsplit(Kb[k0*8 + 2*tq], Kb[k0*8 + 2*tq + 1], h0, l0);
        hsplit(Kb[k1*8 + 2*tq], Kb[k1*8 + 2*tq + 1], h1, l1);
        sKf[e] = make_uint4(h0, l0, h1, l1);
    }
    const float* Vb = &g_V[(size_t)b*NP*CVn];
    for (int e = t; e < SVF_N; e += 256) {
        int c = e >> 7, j = (e >> 5) & 3;
        int k0 = c*16 + 2*tq, ch = j*8 + g;
        u32 h0,l0,h1,l1;
        hsplit(Vb[k0*32 + ch],     Vb[(k0+1)*32 + ch], h0, l0);
        hsplit(Vb[(k0+8)*32 + ch], Vb[(k0+9)*32 + ch], h1, l1);
        sVf[e] = make_uint4(h0, h1, l0, l1);
    }
    for (int i = t; i < CH*CVn; i += 256) {
        int c = i >> 5;
        float ip = ps[c] * rsqrtf(pv[c] + EPSBN);
        sWp[i] = gam * ip * wp[i];
    }
    if (t < CH) {
        float ip = ps[t] * rsqrtf(pv[t] + EPSBN);
        sCp[t] = gam * (bp[t]*ip + pb[t] - pm[t]*ip);
    }
    __syncthreads();

    // ---- Q fragments (hi in A[0..1], lo in A[2..3] = k-dim 8..15)
    int qb = blockIdx.x*256 + wid*32;
    u32 A0[4], A1[4];
    {
        const float* Qb = &g_Q[((size_t)b*HW + qb)*CQn + 2*tq];
        hsplit(Qb[(g    )*8], Qb[(g    )*8 + 1], A0[0], A0[2]);
        hsplit(Qb[(g + 8)*8], Qb[(g + 8)*8 + 1], A0[1], A0[3]);
        hsplit(Qb[(g +16)*8], Qb[(g +16)*8 + 1], A1[0], A1[2]);
        hsplit(Qb[(g +24)*8], Qb[(g +24)*8 + 1], A1[1], A1[3]);
    }

    float mx[2][2], s[2][2], acc[2][4][4];
    #pragma unroll
    for (int h = 0; h < 2; h++)
        #pragma unroll
        for (int r = 0; r < 2; r++) { mx[h][r] = -1e30f; s[h][r] = 0.f; }
    #pragma unroll
    for (int h = 0; h < 2; h++)
        #pragma unroll
        for (int j = 0; j < 4; j++)
            #pragma unroll
            for (int i = 0; i < 4; i++) acc[h][j][i] = 0.f;

    #pragma unroll 1
    for (int c = 0; c < NCH; c++) {
        uint4 kf = sKf[c*32 + lane];
        float l[2][2][4];
        #pragma unroll
        for (int h = 0; h < 2; h++)
            #pragma unroll
            for (int n = 0; n < 2; n++)
                #pragma unroll
                for (int i = 0; i < 4; i++) l[h][n][i] = 0.f;
        // QK^T: hi (B dup) + lo (B upper 0)
        mma16816(l[0][0], A0, kf.x, kf.x); mma16816(l[0][0], A0, kf.y, 0u);
        mma16816(l[0][1], A0, kf.z, kf.z); mma16816(l[0][1], A0, kf.w, 0u);
        mma16816(l[1][0], A1, kf.x, kf.x); mma16816(l[1][0], A1, kf.y, 0u);
        mma16816(l[1][1], A1, kf.z, kf.z); mma16816(l[1][1], A1, kf.w, 0u);

        #pragma unroll
        for (int h = 0; h < 2; h++) {
            u32 P[4]; float f[2];
            #pragma unroll
            for (int r = 0; r < 2; r++) {
                float cm = fmaxf(fmaxf(l[h][0][2*r], l[h][0][2*r+1]),
                                 fmaxf(l[h][1][2*r], l[h][1][2*r+1]));
                cm = fmaxf(cm, __shfl_xor_sync(0xffffffffu, cm, 1));
                cm = fmaxf(cm, __shfl_xor_sync(0xffffffffu, cm, 2));
                float nm = fmaxf(mx[h][r], cm);
                f[r] = ex2f(mx[h][r] - nm);
                mx[h][r] = nm;
                float e0 = ex2f(l[h][0][2*r]   - nm);
                float e1 = ex2f(l[h][0][2*r+1] - nm);
                float e2 = ex2f(l[h][1][2*r]   - nm);
                float e3 = ex2f(l[h][1][2*r+1] - nm);
                s[h][r] = s[h][r]*f[r] + ((e0 + e1) + (e2 + e3));
                P[r]     = pkh(e0, e1);      // a0 / a1
                P[2 + r] = pkh(e2, e3);      // a2 / a3
            }
            #pragma unroll
            for (int j = 0; j < 4; j++) {
                float* a = acc[h][j];
                a[0] *= f[0]; a[1] *= f[0]; a[2] *= f[1]; a[3] *= f[1];
                uint4 vf = sVf[(c*4 + j)*32 + lane];
                mma16816(a, P, vf.x, vf.y);   // P * Vhi
                mma16816(a, P, vf.z, vf.w);   // P * Vlo
            }
        }
    }

    // ---- finalize softmax denominators (quad reduce) + stage G in smem
    float inv[2][2];
    #pragma unroll
    for (int h = 0; h < 2; h++)
        #pragma unroll
        for (int r = 0; r < 2; r++) {
            float ss = s[h][r];
            ss += __shfl_xor_sync(0xffffffffu, ss, 1);
            ss += __shfl_xor_sync(0xffffffffu, ss, 2);
            inv[h][r] = 1.0f / ss;
        }
    __syncthreads();   // all fragment reads done -> safe to alias sG
    #pragma unroll
    for (int h = 0; h < 2; h++) {
        int r0 = (wid*32 + h*16 + g)*33;
        int r1 = r0 + 8*33;
        #pragma unroll
        for (int j = 0; j < 4; j++) {
            int cb = j*8 + 2*tq;
            sG[r0 + cb    ] = acc[h][j][0]*inv[h][0];
            sG[r0 + cb + 1] = acc[h][j][1]*inv[h][0];
            sG[r1 + cb    ] = acc[h][j][2]*inv[h][1];
            sG[r1 + cb + 1] = acc[h][j][3]*inv[h][1];
        }
    }
    __syncthreads();

    // ---- projection (f32x2) + residual; 1 query/thread, coalesced I/O
    u64 gp[16];
    {
        const float* gr = &sG[t*33];
        #pragma unroll
        for (int i = 0; i < 16; i++) gp[i] = pk2(gr[2*i], gr[2*i+1]);
    }
    size_t base = (size_t)b*CH*HW + (size_t)blockIdx.x*256 + t;
    #pragma unroll 4
    for (int c2 = 0; c2 < CH; c2++) {
        const u64* w2 = (const u64*)&sWp[c2*32];
        u64 d = 0ULL;
        #pragma unroll
        for (int i = 0; i < 16; i++) d = ffma2(gp[i], w2[i], d);
        float lo, hi; upk2(d, lo, hi);
        float val = lo + hi + sCp[c2];
        out[base + (size_t)c2*HW] = __ldg(&x[base + (size_t)c2*HW]) + val;
    }
}

// ---------------- launch ----------------
extern "C" void kernel_launch(void* const* d_in, const int* in_sizes, int n_in,
                              void* d_out, int out_size)
{
    (void)in_sizes; (void)n_in; (void)out_size;
    const float* x   = (const float*)d_in[0];
    const float* mem = (const float*)d_in[1];

    cudaFuncSetAttribute(attn_kernel,
                         cudaFuncAttributeMaxDynamicSharedMemorySize, SMEM_ATTN);

    prep_kernel<<<BATCH*32, 256>>>(mem,
        (const float*)d_in[2],  (const float*)d_in[3],  (const float*)d_in[4],
        (const float*)d_in[5],  (const float*)d_in[6],  (const float*)d_in[7],
        (const float*)d_in[8],  (const float*)d_in[9],  (const float*)d_in[10],
        (const float*)d_in[11], (const float*)d_in[12], (const float*)d_in[13],
        (const float*)d_in[14], (const float*)d_in[15], (const float*)d_in[16],
        (const float*)d_in[17], (const float*)d_in[18], (const float*)d_in[19]);

    attn_kernel<<<dim3(16, BATCH), 256, SMEM_ATTN>>>(x, (float*)d_out,
        (const float*)d_in[20], (const float*)d_in[21], (const float*)d_in[22],
        (const float*)d_in[23], (const float*)d_in[24], (const float*)d_in[25],
        (const float*)d_in[26]);
}

// round 6
// speedup vs baseline: 2.4018x; 1.0431x over previous
#include <cuda_runtime.h>
#include <cstdint>

typedef unsigned int u32;
typedef unsigned long long u64;

#define BATCH 8
#define CH    64
#define HW    4096
#define CQn   8
#define CVn   32
#define NP    1024
#define NCH   64          // 16-key chunks
#define EPSBN 1e-5f
#define LOG2E 1.4426950408889634f

__device__ float g_Q[(size_t)BATCH*HW*CQn];   // [b][n][8]
__device__ float g_K[(size_t)BATCH*NP*CQn];   // [b][m][8]  (x log2e)
__device__ float g_V[(size_t)BATCH*NP*CVn];   // [b][m][32]

// ---------------- helpers ----------------
__device__ __forceinline__ u64 pk2(float lo, float hi) {
    u64 r; asm("mov.b64 %0,{%1,%2};" : "=l"(r) : "f"(lo), "f"(hi)); return r;
}
__device__ __forceinline__ void upk2(u64 v, float& lo, float& hi) {
    asm("mov.b64 {%0,%1},%2;" : "=f"(lo), "=f"(hi) : "l"(v));
}
__device__ __forceinline__ u64 ffma2(u64 a, u64 b, u64 c) {
    u64 d; asm("fma.rn.f32x2 %0,%1,%2,%3;" : "=l"(d) : "l"(a), "l"(b), "l"(c)); return d;
}
__device__ __forceinline__ float ex2f(float x) {
    float y; asm("ex2.approx.f32 %0,%1;" : "=f"(y) : "f"(x)); return y;
}
__device__ __forceinline__ u32 pkh(float a, float b) {   // a->lo half, b->hi half
    u32 r; asm("cvt.rn.f16x2.f32 %0,%1,%2;" : "=r"(r) : "f"(b), "f"(a)); return r;
}
__device__ __forceinline__ void hsplit(float a, float b, u32& hi, u32& lo) {
    u32 h = pkh(a, b);
    float fa, fb;
    asm("{.reg .b16 x,y; mov.b32 {x,y},%2; cvt.f32.f16 %0,x; cvt.f32.f16 %1,y;}"
        : "=f"(fa), "=f"(fb) : "r"(h));
    hi = h; lo = pkh(a - fa, b - fb);
}
__device__ __forceinline__ void mma16816(float* d, const u32* a, u32 b0, u32 b1) {
    asm("mma.sync.aligned.m16n8k16.row.col.f32.f16.f16.f32 "
        "{%0,%1,%2,%3},{%4,%5,%6,%7},{%8,%9},{%0,%1,%2,%3};"
        : "+f"(d[0]), "+f"(d[1]), "+f"(d[2]), "+f"(d[3])
        : "r"(a[0]), "r"(a[1]), "r"(a[2]), "r"(a[3]), "r"(b0), "r"(b1));
}

// ---------------- kernel 1: Q + pooled K/V (unchanged, proven) ----------------
__global__ __launch_bounds__(256) void prep_kernel(
    const float* __restrict__ mem,
    const float* __restrict__ wq, const float* __restrict__ bq,
    const float* __restrict__ qs, const float* __restrict__ qb,
    const float* __restrict__ qm, const float* __restrict__ qv,
    const float* __restrict__ wk, const float* __restrict__ bk,
    const float* __restrict__ ks, const float* __restrict__ kb,
    const float* __restrict__ km, const float* __restrict__ kv,
    const float* __restrict__ wv, const float* __restrict__ bv,
    const float* __restrict__ vs, const float* __restrict__ vb,
    const float* __restrict__ vm, const float* __restrict__ vv)
{
    __shared__ float tile[CH*128];
    __shared__ float wqs[CQn*CH], wks[CQn*CH], wvs[CVn*CH];
    __shared__ float cqs[CQn], cks[CQn], cvs[CVn];

    int t  = threadIdx.x;
    int b  = blockIdx.x >> 5;
    int h2 = blockIdx.x & 31;

    for (int i = t; i < CQn*CH; i += 256) {
        int c = i >> 6;
        float iq = qs[c] * rsqrtf(qv[c] + EPSBN);
        float ik = ks[c] * rsqrtf(kv[c] + EPSBN);
        wqs[i] = wq[i] * iq;
        wks[i] = wk[i] * ik * LOG2E;
    }
    for (int i = t; i < CVn*CH; i += 256) {
        int c = i >> 6;
        float iv = vs[c] * rsqrtf(vv[c] + EPSBN);
        wvs[i] = wv[i] * iv;
    }
    if (t < CQn) {
        float iq = qs[t] * rsqrtf(qv[t] + EPSBN);
        float ik = ks[t] * rsqrtf(kv[t] + EPSBN);
        cqs[t] = bq[t]*iq + qb[t] - qm[t]*iq;
        cks[t] = (bk[t]*ik + kb[t] - km[t]*ik) * LOG2E;
    }
    if (t < CVn) {
        float iv = vs[t] * rsqrtf(vv[t] + EPSBN);
        cvs[t] = bv[t]*iv + vb[t] - vm[t]*iv;
    }

    const float4* src = (const float4*)(mem + (size_t)b*CH*HW + (size_t)h2*128);
    float4* t4 = (float4*)tile;
    for (int i = t; i < CH*32; i += 256) {
        int c = i >> 5, j = i & 31;
        t4[i] = src[(size_t)c*(HW/4) + j];
    }
    __syncthreads();

    {   // Q
        int p = t & 127, half = t >> 7;
        int oc0 = half * 4;
        float a0 = 0.f, a1 = 0.f, a2 = 0.f, a3 = 0.f;
        const float* w0 = &wqs[oc0*CH];
        #pragma unroll 8
        for (int ch = 0; ch < CH; ch++) {
            float m = tile[ch*128 + p];
            a0 += w0[ch]*m; a1 += w0[CH+ch]*m;
            a2 += w0[2*CH+ch]*m; a3 += w0[3*CH+ch]*m;
        }
        size_t n = (size_t)b*HW + h2*128 + p;
        float4 o = make_float4(a0 + cqs[oc0], a1 + cqs[oc0+1],
                               a2 + cqs[oc0+2], a3 + cqs[oc0+3]);
        *(float4*)&g_Q[n*CQn + oc0] = o;
    }
    {   // K pooled
        int i = t & 31, oc = t >> 5;
        float a0 = 0.f, a1 = 0.f, a2 = 0.f, a3 = 0.f;
        const float* w = &wks[oc*CH];
        int p0 = 2*i, p2 = 64 + 2*i;
        #pragma unroll 4
        for (int ch = 0; ch < CH; ch++) {
            float wv_ = w[ch];
            const float* tr = &tile[ch*128];
            a0 += wv_*tr[p0]; a1 += wv_*tr[p0+1];
            a2 += wv_*tr[p2]; a3 += wv_*tr[p2+1];
        }
        float mx = fmaxf(fmaxf(a0,a1), fmaxf(a2,a3)) + cks[oc];
        g_K[((size_t)b*NP + h2*32 + i)*CQn + oc] = mx;
    }
    {   // V pooled
        int i = t & 31, gr = t >> 5;
        int oc0 = gr * 4;
        float acc[4][4];
        #pragma unroll
        for (int a = 0; a < 4; a++)
            #pragma unroll
            for (int c = 0; c < 4; c++) acc[a][c] = 0.f;
        int p0 = 2*i, p2 = 64 + 2*i;
        #pragma unroll 2
        for (int ch = 0; ch < CH; ch++) {
            const float* tr = &tile[ch*128];
            float m0 = tr[p0], m1 = tr[p0+1], m2 = tr[p2], m3 = tr[p2+1];
            #pragma unroll
            for (int a = 0; a < 4; a++) {
                float wv_ = wvs[(oc0+a)*CH + ch];
                acc[a][0] += wv_*m0; acc[a][1] += wv_*m1;
                acc[a][2] += wv_*m2; acc[a][3] += wv_*m3;
            }
        }
        float4 o; float* op = &o.x;
        #pragma unroll
        for (int a = 0; a < 4; a++)
            op[a] = fmaxf(fmaxf(acc[a][0],acc[a][1]),
                          fmaxf(acc[a][2],acc[a][3])) + cvs[oc0+a];
        *(float4*)&g_V[((size_t)b*NP + h2*32 + i)*CVn + oc0] = o;
    }
}

// ---------------- kernel 2: tensor-core flash attention ----------------
// 8 warps x 16 queries = 128 q/CTA; grid (32, BATCH) = 256 CTAs, 2 CTAs/SM.
#define SKF_N 2048                       // NCH*32 uint4  (K hi/lo)
#define SVF_N 8192                       // NCH*4*32 uint2 (V hi only)
#define SMEM_ATTN (SKF_N*16 + SVF_N*8 + CH*CVn*4 + CH*4)

__global__ __launch_bounds__(256, 2) void attn_kernel(
    const float* __restrict__ x, float* __restrict__ out,
    const float* __restrict__ wp, const float* __restrict__ bp,
    const float* __restrict__ ps, const float* __restrict__ pb,
    const float* __restrict__ pm, const float* __restrict__ pv,
    const float* __restrict__ gamma)
{
    extern __shared__ char smem[];
    uint4* sKf = (uint4*)smem;           // [chunk][lane] {kh0,kl0,kh1,kl1}
    uint2* sVf = (uint2*)(sKf + SKF_N);  // [chunk][j][lane] {vh01, vh89}
    float* sWp = (float*)(sVf + SVF_N);  // [ch][32]
    float* sCp = sWp + CH*CVn;
    float* sG  = (float*)smem;           // alias after loop: [128 q][stride 33]

    int t = threadIdx.x, lane = t & 31, wid = t >> 5;
    int g = lane >> 2, tq = lane & 3;
    int b = blockIdx.y;
    float gam = gamma[0];

    // ---- copy-in: build K (hi/lo) and V (hi) MMA fragments
    const float* Kb = &g_K[(size_t)b*NP*CQn];
    for (int e = t; e < SKF_N; e += 256) {
        int c = e >> 5;
        int k0 = c*16 + g, k1 = k0 + 8;
        u32 h0,l0,h1,l1;
        hsplit(Kb[k0*8 + 2*tq], Kb[k0*8 + 2*tq + 1], h0, l0);
        hsplit(Kb[k1*8 + 2*tq], Kb[k1*8 + 2*tq + 1], h1, l1);
        sKf[e] = make_uint4(h0, l0, h1, l1);
    }
    const float* Vb = &g_V[(size_t)b*NP*CVn];
    for (int e = t; e < SVF_N; e += 256) {
        int c = e >> 7, j = (e >> 5) & 3;
        int k0 = c*16 + 2*tq, ch = j*8 + g;
        u32 v0 = pkh(Vb[k0*32 + ch],     Vb[(k0+1)*32 + ch]);
        u32 v1 = pkh(Vb[(k0+8)*32 + ch], Vb[(k0+9)*32 + ch]);
        sVf[e] = make_uint2(v0, v1);
    }
    for (int i = t; i < CH*CVn; i += 256) {
        int c = i >> 5;
        float ip = ps[c] * rsqrtf(pv[c] + EPSBN);
        sWp[i] = gam * ip * wp[i];
    }
    if (t < CH) {
        float ip = ps[t] * rsqrtf(pv[t] + EPSBN);
        sCp[t] = gam * (bp[t]*ip + pb[t] - pm[t]*ip);
    }
    __syncthreads();

    // ---- Q fragments: 16 queries/warp (hi -> k 0..7, lo -> k 8..15)
    int qb = blockIdx.x*128 + wid*16;
    u32 A0[4];
    {
        const float* Qb = &g_Q[((size_t)b*HW + qb)*CQn + 2*tq];
        hsplit(Qb[(g    )*8], Qb[(g    )*8 + 1], A0[0], A0[2]);
        hsplit(Qb[(g + 8)*8], Qb[(g + 8)*8 + 1], A0[1], A0[3]);
    }

    float mx[2] = {-1e30f, -1e30f}, s[2] = {0.f, 0.f};
    float acc[4][4];
    #pragma unroll
    for (int j = 0; j < 4; j++)
        #pragma unroll
        for (int i = 0; i < 4; i++) acc[j][i] = 0.f;

    #pragma unroll 1
    for (int c = 0; c < NCH; c++) {
        uint4 kf = sKf[c*32 + lane];
        float l[2][4];
        #pragma unroll
        for (int n = 0; n < 2; n++)
            #pragma unroll
            for (int i = 0; i < 4; i++) l[n][i] = 0.f;
        // QK^T: (Qhi+Qlo)*Khi + Qhi*Klo
        mma16816(l[0], A0, kf.x, kf.x); mma16816(l[0], A0, kf.y, 0u);
        mma16816(l[1], A0, kf.z, kf.z); mma16816(l[1], A0, kf.w, 0u);

        u32 P[4]; float f[2];
        #pragma unroll
        for (int r = 0; r < 2; r++) {
            float cm = fmaxf(fmaxf(l[0][2*r], l[0][2*r+1]),
                             fmaxf(l[1][2*r], l[1][2*r+1]));
            cm = fmaxf(cm, __shfl_xor_sync(0xffffffffu, cm, 1));
            cm = fmaxf(cm, __shfl_xor_sync(0xffffffffu, cm, 2));
            float nm = fmaxf(mx[r], cm);
            f[r] = ex2f(mx[r] - nm);
            mx[r] = nm;
            float e0 = ex2f(l[0][2*r]   - nm);
            float e1 = ex2f(l[0][2*r+1] - nm);
            float e2 = ex2f(l[1][2*r]   - nm);
            float e3 = ex2f(l[1][2*r+1] - nm);
            s[r] = s[r]*f[r] + ((e0 + e1) + (e2 + e3));
            P[r]     = pkh(e0, e1);
            P[2 + r] = pkh(e2, e3);
        }
        #pragma unroll
        for (int j = 0; j < 4; j++) {
            float* a = acc[j];
            a[0] *= f[0]; a[1] *= f[0]; a[2] *= f[1]; a[3] *= f[1];
            uint2 vf = sVf[(c*4 + j)*32 + lane];
            mma16816(a, P, vf.x, vf.y);
        }
    }

    // ---- finalize denominators (quad reduce) + stage G in smem
    float inv[2];
    #pragma unroll
    for (int r = 0; r < 2; r++) {
        float ss = s[r];
        ss += __shfl_xor_sync(0xffffffffu, ss, 1);
        ss += __shfl_xor_sync(0xffffffffu, ss, 2);
        inv[r] = 1.0f / ss;
    }
    __syncthreads();   // fragment reads done -> safe to alias sG
    {
        int r0 = (wid*16 + g)*33;
        int r1 = r0 + 8*33;
        #pragma unroll
        for (int j = 0; j < 4; j++) {
            int cb = j*8 + 2*tq;
            sG[r0 + cb    ] = acc[j][0]*inv[0];
            sG[r0 + cb + 1] = acc[j][1]*inv[0];
            sG[r1 + cb    ] = acc[j][2]*inv[1];
            sG[r1 + cb + 1] = acc[j][3]*inv[1];
        }
    }
    __syncthreads();

    // ---- projection (f32x2) + residual; 2 threads/query (32 ch each)
    int q = t & 127, half = t >> 7;
    u64 gp[16];
    {
        const float* gr = &sG[q*33];
        #pragma unroll
        for (int i = 0; i < 16; i++) gp[i] = pk2(gr[2*i], gr[2*i+1]);
    }
    size_t base = (size_t)b*CH*HW + (size_t)blockIdx.x*128 + q;
    int c0 = half*32;
    #pragma unroll 4
    for (int cc = 0; cc < 32; cc++) {
        int c2 = c0 + cc;
        const u64* w2 = (const u64*)&sWp[c2*32];
        u64 d = 0ULL;
        #pragma unroll
        for (int i = 0; i < 16; i++) d = ffma2(gp[i], w2[i], d);
        float lo, hi; upk2(d, lo, hi);
        float val = lo + hi + sCp[c2];
        out[base + (size_t)c2*HW] = __ldg(&x[base + (size_t)c2*HW]) + val;
    }
}

// ---------------- launch ----------------
extern "C" void kernel_launch(void* const* d_in, const int* in_sizes, int n_in,
                              void* d_out, int out_size)
{
    (void)in_sizes; (void)n_in; (void)out_size;
    const float* x   = (const float*)d_in[0];
    const float* mem = (const float*)d_in[1];

    cudaFuncSetAttribute(attn_kernel,
                         cudaFuncAttributeMaxDynamicSharedMemorySize, SMEM_ATTN);

    prep_kernel<<<BATCH*32, 256>>>(mem,
        (const float*)d_in[2],  (const float*)d_in[3],  (const float*)d_in[4],
        (const float*)d_in[5],  (const float*)d_in[6],  (const float*)d_in[7],
        (const float*)d_in[8],  (const float*)d_in[9],  (const float*)d_in[10],
        (const float*)d_in[11], (const float*)d_in[12], (const float*)d_in[13],
        (const float*)d_in[14], (const float*)d_in[15], (const float*)d_in[16],
        (const float*)d_in[17], (const float*)d_in[18], (const float*)d_in[19]);

    attn_kernel<<<dim3(32, BATCH), 256, SMEM_ATTN>>>(x, (float*)d_out,
        (const float*)d_in[20], (const float*)d_in[21], (const float*)d_in[22],
        (const float*)d_in[23], (const float*)d_in[24], (const float*)d_in[25],
        (const float*)d_in[26]);
}